// round 14
// baseline (speedup 1.0000x reference)
#include <cuda_runtime.h>
#include <cuda_bf16.h>
#include <math.h>
#include <stdint.h>

#define Tn 512
#define Bn 64
#define Hn 512
#define G4 2048

__device__ float    g_xg[2ULL * Tn * G4 * Bn];       // [dir][t][gate_row][b]
__device__ uint32_t g_xphi[(size_t)Tn * 512 * 64];   // [t][kpair][b]
__device__ uint32_t g_xplo[(size_t)Tn * 512 * 64];
__device__ uint32_t g_wphi[3145728];
__device__ uint32_t g_wplo[3145728];
__device__ uint32_t g_hhi[2][2][256][64];            // [buf][dir][jpair][b]
__device__ uint32_t g_hlo[2][2][256][64];
__device__ unsigned long long g_cnt[2] = {0ULL, 0ULL};
__device__ unsigned long long g_rel[2] = {0ULL, 0ULL};

__device__ __forceinline__ void mma16(float* c, const uint32_t* a, uint32_t b0, uint32_t b1) {
    asm volatile("mma.sync.aligned.m16n8k16.row.col.f32.bf16.bf16.f32 "
        "{%0,%1,%2,%3}, {%4,%5,%6,%7}, {%8,%9}, {%0,%1,%2,%3};\n"
        : "+f"(c[0]), "+f"(c[1]), "+f"(c[2]), "+f"(c[3])
        : "r"(a[0]), "r"(a[1]), "r"(a[2]), "r"(a[3]), "r"(b0), "r"(b1));
}
__device__ __forceinline__ uint32_t packbf(float a, float b) {
    __nv_bfloat16 x = __float2bfloat16_rn(a), y = __float2bfloat16_rn(b);
    return ((uint32_t)__bfloat16_as_ushort(y) << 16) | __bfloat16_as_ushort(x);
}
__device__ __forceinline__ float bfr(float v) {
    return __bfloat162float(__float2bfloat16_rn(v));
}
__device__ __forceinline__ float sigf(float x) {
    return __fdividef(1.0f, 1.0f + __expf(-x));
}
__device__ __forceinline__ float tanhfast(float x) {
    x = fminf(fmaxf(x, -15.0f), 15.0f);
    float t = __expf(-2.0f * x);
    return __fdividef(1.0f - t, 1.0f + t);
}
__device__ __forceinline__ unsigned long long ld64acq(const unsigned long long* p) {
    unsigned long long v;
    asm volatile("ld.acquire.gpu.global.u64 %0, [%1];" : "=l"(v) : "l"(p));
    return v;
}
__device__ __forceinline__ void red64(unsigned long long* p) {
    asm volatile("red.relaxed.gpu.global.add.u64 [%0], 1;" :: "l"(p) : "memory");
}
__device__ __forceinline__ void st64rel(unsigned long long* p, unsigned long long v) {
    asm volatile("st.relaxed.gpu.global.u64 [%0], %1;" :: "l"(p), "l"(v));
}

// ---- pack W_ih ---------------------------------------------------------------
__global__ void pack_w(const float* __restrict__ W, uint32_t* __restrict__ hi,
                       uint32_t* __restrict__ lo)
{
    size_t idx = (size_t)blockIdx.x * 256 + threadIdx.x;
    float2 w = *(const float2*)(W + 2 * idx);
    hi[idx] = packbf(w.x, w.y);
    lo[idx] = packbf(w.x - bfr(w.x), w.y - bfr(w.y));
}

// ---- pack x ------------------------------------------------------------------
__global__ __launch_bounds__(256, 4) void pack_x(const float* __restrict__ x)
{
    __shared__ float smx[64 * 68];
    const int t = blockIdx.x, tid = threadIdx.x;
    for (int kb = 0; kb < 512; kb += 64) {
        __syncthreads();
#pragma unroll
        for (int i = 0; i < 4; ++i) {
            int idx = tid + i * 256, b = idx >> 4, f = idx & 15;
            float4 v = *(const float4*)(x + ((size_t)t * 64 + b) * 512 + kb + 4 * f);
            *(float4*)(smx + b * 68 + 4 * f) = v;
        }
        __syncthreads();
#pragma unroll
        for (int i = 0; i < 8; ++i) {
            int idx = tid + i * 256, kp = idx >> 6, b = idx & 63;
            float v0 = smx[b * 68 + 2 * kp], v1 = smx[b * 68 + 2 * kp + 1];
            size_t o = ((size_t)t * 512 + (kb >> 1) + kp) * 64 + b;
            g_xphi[o] = packbf(v0, v1);
            g_xplo[o] = packbf(v0 - bfr(v0), v1 - bfr(v1));
        }
    }
}

// ---- input GEMM: bf16x3, prepacked (unchanged) -------------------------------
#define AST 20
#define IN_SMEM (14848 * 4)

__global__ __launch_bounds__(256, 2)
void input_gemm_mma(const uint32_t* __restrict__ Whi, const uint32_t* __restrict__ Wlo,
                    const float* __restrict__ bih, const float* __restrict__ bhh,
                    int KP, int dir)
{
    extern __shared__ uint32_t sm[];
    uint32_t *AH = sm, *AL = sm + 5120, *BH = sm + 10240, *BL = sm + 12544;
    __shared__ float sbias[128];

    const int t = blockIdx.y, n0 = blockIdx.x * 128;
    const int tid = threadIdx.x, wid = tid >> 5, lane = tid & 31;
    const int gid = lane >> 2, tg = lane & 3;
    const int wm = wid >> 1, wn = wid & 1;
    const int NC = KP >> 4;

    if (tid < 128) sbias[tid] = bih[n0 + tid] + bhh[n0 + tid];
    const uint32_t* XH = g_xphi + (size_t)t * 512 * 64;
    const uint32_t* XL = g_xplo + (size_t)t * 512 * 64;

    uint4 ar[4], br[2];
    float acc[2][4][4];
#pragma unroll
    for (int a = 0; a < 2; ++a)
#pragma unroll
        for (int b = 0; b < 4; ++b)
#pragma unroll
            for (int c = 0; c < 4; ++c) acc[a][b][c] = 0.f;

    auto ldc = [&](int s) {
        const int k0 = s * 16;
#pragma unroll
        for (int i = 0; i < 4; ++i) {
            int j = tid + (i & 1) * 256, r = j >> 2, c = j & 3;
            const uint32_t* src = (i >> 1) ? Wlo : Whi;
            ar[i] = *(const uint4*)(src + (size_t)(n0 + r) * KP + k0 + 4 * c);
        }
#pragma unroll
        for (int i = 0; i < 2; ++i) {
            int r = tid >> 4, c = tid & 15;
            const uint32_t* src = i ? XL : XH;
            br[i] = *(const uint4*)(src + (size_t)(k0 + r) * 64 + 4 * c);
        }
    };
    auto stc = [&](int p) {
#pragma unroll
        for (int i = 0; i < 4; ++i) {
            int j = tid + (i & 1) * 256, r = j >> 2, c = j & 3;
            uint32_t* dst = (i >> 1) ? AL : AH;
            *(uint4*)(dst + p * 2560 + r * AST + 4 * c) = ar[i];
        }
#pragma unroll
        for (int i = 0; i < 2; ++i) {
            int r = tid >> 4, c = tid & 15;
            uint32_t* dst = i ? BL : BH;
            *(uint4*)(dst + p * 1152 + r * 72 + 4 * c) = br[i];
        }
    };

    ldc(0); stc(0); __syncthreads();

    for (int s = 0; s < NC; ++s) {
        const int p = s & 1;
        if (s + 1 < NC) ldc(s + 1);
        const uint32_t* Ah = AH + p * 2560;
        const uint32_t* Al = AL + p * 2560;
        const uint32_t* Bh = BH + p * 1152;
        const uint32_t* Bl = BL + p * 1152;
#pragma unroll
        for (int ks = 0; ks < 2; ++ks) {
            const int kb = ks * 8;
            uint32_t ahi[2][4], alo[2][4];
#pragma unroll
            for (int mt = 0; mt < 2; ++mt) {
                int r = wm * 32 + mt * 16 + gid;
                ahi[mt][0] = Ah[r * AST + kb + tg];
                ahi[mt][1] = Ah[(r + 8) * AST + kb + tg];
                ahi[mt][2] = Ah[r * AST + kb + tg + 4];
                ahi[mt][3] = Ah[(r + 8) * AST + kb + tg + 4];
                alo[mt][0] = Al[r * AST + kb + tg];
                alo[mt][1] = Al[(r + 8) * AST + kb + tg];
                alo[mt][2] = Al[r * AST + kb + tg + 4];
                alo[mt][3] = Al[(r + 8) * AST + kb + tg + 4];
            }
#pragma unroll
            for (int nt = 0; nt < 4; ++nt) {
                int col = wn * 32 + nt * 8 + gid;
                uint32_t bh0 = Bh[(kb + tg) * 72 + col];
                uint32_t bh1 = Bh[(kb + tg + 4) * 72 + col];
                uint32_t bl0 = Bl[(kb + tg) * 72 + col];
                uint32_t bl1 = Bl[(kb + tg + 4) * 72 + col];
#pragma unroll
                for (int mt = 0; mt < 2; ++mt) {
                    mma16(acc[mt][nt], ahi[mt], bh0, bh1);
                    mma16(acc[mt][nt], ahi[mt], bl0, bl1);
                    mma16(acc[mt][nt], alo[mt], bh0, bh1);
                }
            }
        }
        __syncthreads();
        if (s + 1 < NC) { stc(1 - p); __syncthreads(); }
    }

    float* xgd = g_xg + (size_t)dir * Tn * G4 * Bn + (size_t)t * G4 * Bn;
#pragma unroll
    for (int mt = 0; mt < 2; ++mt) {
#pragma unroll
        for (int half = 0; half < 2; ++half) {
            int m = wm * 32 + mt * 16 + gid + half * 8;
            float bias = sbias[m];
            float* row = xgd + (size_t)(n0 + m) * Bn;
#pragma unroll
            for (int nt = 0; nt < 4; ++nt) {
                int b = wn * 32 + nt * 8 + 2 * tg;
                *(float2*)(row + b) = make_float2(acc[mt][nt][2 * half] + bias,
                                                  acc[mt][nt][2 * half + 1] + bias);
            }
        }
    }
}

// ---- recurrent kernel: 32 CTAs/dir x 512 thr, 16 j's each, halved L2 traffic -
// smem u32: W2hi[64][264], W2lo[64][264], BH[2][64][72], BL[2][64][72],
//           Gs aliased on BH buf0, cs[16][64], msk[64]. 213,248 B.
#define W2LO_OFF 16896
#define BB_HI    33792
#define BB_LO    43008
#define GSO      33792
#define CS_OFF   52224
#define MSK_OFF  53248
#define REC_SMEM (53312 * 4)

__global__ __launch_bounds__(512, 1)
void lstm_rec_mma(const float* __restrict__ whh_f, const float* __restrict__ whh_b,
                  const float* __restrict__ mask, float* __restrict__ outext,
                  int final_layer)
{
    extern __shared__ uint32_t smw[];
    uint32_t* W2hi = smw;
    uint32_t* W2lo = smw + W2LO_OFF;
    uint32_t* BHs  = smw + BB_HI;
    uint32_t* BLs  = smw + BB_LO;
    float*    Gs   = (float*)(smw + GSO);
    float*    cs   = (float*)(smw + CS_OFF);
    float*    msk  = (float*)(smw + MSK_OFF);
    __shared__ unsigned long long s_tgt;

    const int cta = blockIdx.x, tid = threadIdx.x;
    const int dir = cta >> 5;
    const int c   = cta & 31;
    const int j0  = c * 16;
    const int lane = tid & 31, wid = tid >> 5;
    const int gid = lane >> 2, tg = lane & 3;
    const int wm = wid >> 2, wn = wid & 3;       // 4 x 4 warp grid
    const int colb = wn * 16;

    const float* __restrict__ Whh = dir ? whh_b : whh_f;
    const float* __restrict__ xgd = g_xg + (size_t)dir * Tn * G4 * Bn;

    if (tid == 0) s_tgt = ld64acq(&g_rel[dir]) + 1ULL;

    // pack W_hh slice: 64 rows (gate = r>>4, j = j0 + (r&15)), u64-paired planes
    for (int i = tid; i < 16384; i += 512) {
        int r = i >> 8, p = i & 255;
        int grow = (r >> 4) * Hn + j0 + (r & 15);
        float2 w = *(const float2*)(Whh + (size_t)grow * Hn + 2 * p);
        int a = r * 264 + (p >> 3) * 8 + 2 * (p & 3) + ((p >> 2) & 1);
        W2hi[a] = packbf(w.x, w.y);
        W2lo[a] = packbf(w.x - bfr(w.x), w.y - bfr(w.y));
    }
    {   // zero own h slice (8 jpairs x 64 b = 512 entries, 1/thread)
        int p = tid >> 6, b = tid & 63;
        g_hhi[0][dir][c * 8 + p][b] = 0u;
        g_hlo[0][dir][c * 8 + p][b] = 0u;
    }
    for (int i = tid; i < 1024; i += 512) cs[i] = 0.0f;
    __syncthreads();
    if (tid == 0) {
        __threadfence();
        unsigned long long tgt = s_tgt;
        red64(&g_cnt[dir]);
        unsigned long long need = tgt << 5;      // 32 arrivals
        unsigned long long v = ld64acq(&g_cnt[dir]);
        while (v < need) { __nanosleep(32); v = ld64acq(&g_cnt[dir]); }
        st64rel(&g_rel[dir], tgt);
        __threadfence();
        s_tgt = tgt + 1ULL;
    }
    __syncthreads();

    float nxt[2][4];
    auto ldxg = [&](int t, float v[2][4]) {
        const size_t xb = (size_t)t * G4 * Bn;
        const float* p0 = xgd + xb + ((size_t)wm * Hn + j0 + gid) * Bn;
        const float* p1 = xgd + xb + ((size_t)wm * Hn + j0 + gid + 8) * Bn;
#pragma unroll
        for (int nt = 0; nt < 2; ++nt) {
            int col = colb + nt * 8 + 2 * tg;
            float2 u = *(const float2*)(p0 + col);
            float2 w = *(const float2*)(p1 + col);
            v[nt][0] = u.x; v[nt][1] = u.y; v[nt][2] = w.x; v[nt][3] = w.y;
        }
    };
    ldxg(dir ? (Tn - 1) : 0, nxt);

    for (int s = 0; s < Tn; ++s) {
        const int t  = dir ? (Tn - 1 - s) : s;
        const int rb = s & 1;
        if (tid < 16)
            ((float4*)msk)[tid] = ((const float4*)(mask + (size_t)t * Bn))[tid];

        float c0[2][4];
#pragma unroll
        for (int nt = 0; nt < 2; ++nt)
#pragma unroll
            for (int e = 0; e < 4; ++e) c0[nt][e] = nxt[nt][e];

        const uint32_t* srcHi = &g_hhi[rb][dir][0][0];
        const uint32_t* srcLo = &g_hlo[rb][dir][0][0];

        uint4 ph[2], pl[2];
        auto pollload = [&](int ch) {
#pragma unroll
            for (int i = 0; i < 2; ++i) {
                int idx = tid + i * 512, q = idx >> 4, c4 = (idx & 15) * 4;
                int ap = ch * 64 + q;
                ph[i] = *(const uint4*)(srcHi + (size_t)ap * 64 + c4);
                pl[i] = *(const uint4*)(srcLo + (size_t)ap * 64 + c4);
            }
        };
        auto store = [&](int buf) {
            uint32_t* BH2 = BHs + buf * 4608;
            uint32_t* BL2 = BLs + buf * 4608;
#pragma unroll
            for (int i = 0; i < 2; ++i) {
                int idx = tid + i * 512, q = idx >> 4, c4 = (idx & 15) * 4;
                *(uint4*)(BH2 + q * 72 + c4) = ph[i];
                *(uint4*)(BL2 + q * 72 + c4) = pl[i];
            }
        };

        pollload(0);
        store(0);
        __syncthreads();

        const uint2* A2h = (const uint2*)W2hi;
        const uint2* A2l = (const uint2*)W2lo;

        for (int ch = 0; ch < 4; ++ch) {
            const int buf = ch & 1;
            if (ch < 3) pollload(ch + 1);
            const uint32_t* BH = BHs + buf * 4608;
            const uint32_t* BL = BLs + buf * 4608;
#pragma unroll
            for (int kt = 0; kt < 8; ++kt) {
                const int g  = ch * 8 + kt;
                const int ra = wm * 16 + gid;
                const int i0 = ra * 132 + g * 4 + tg;
                uint2 h0 = A2h[i0];
                uint2 h1 = A2h[i0 + 8 * 132];
                uint2 l0 = A2l[i0];
                uint2 l1 = A2l[i0 + 8 * 132];
                uint32_t ahi[4] = { h0.x, h1.x, h0.y, h1.y };
                uint32_t alo[4] = { l0.x, l1.x, l0.y, l1.y };
                const int qb = kt * 8;                 // LOCAL chunk row
#pragma unroll
                for (int nt = 0; nt < 2; ++nt) {
                    const int col = colb + nt * 8 + gid;
                    uint32_t bh0 = BH[(qb + tg) * 72 + col];
                    uint32_t bh1 = BH[(qb + tg + 4) * 72 + col];
                    uint32_t bl0 = BL[(qb + tg) * 72 + col];
                    uint32_t bl1 = BL[(qb + tg + 4) * 72 + col];
                    mma16(c0[nt], ahi, bh0, bh1);
                    mma16(c0[nt], ahi, bl0, bl1);
                    mma16(c0[nt], alo, bh0, bh1);
                }
            }
            if (ch < 3) { store(buf ^ 1); __syncthreads(); }
        }
        // last chunk read buf1; Gs aliases buf0 region — disjoint, safe.

#pragma unroll
        for (int nt = 0; nt < 2; ++nt) {
            int col = colb + nt * 8 + 2 * tg;
            int r = wm * 16 + gid;
            *(float2*)&Gs[r * 66 + col]       = make_float2(c0[nt][0], c0[nt][1]);
            *(float2*)&Gs[(r + 8) * 66 + col] = make_float2(c0[nt][2], c0[nt][3]);
        }
        __syncthreads();

        // ---- epilogue: gates for 2 j's per thread ---------------------------
        const int jp = tid >> 6, b = tid & 63;       // jp 0..7
        const float m = msk[b];
        float hv[2];
#pragma unroll
        for (int e = 0; e < 2; ++e) {
            const int jl = 2 * jp + e;               // 0..15
            const float ii = sigf(Gs[jl * 66 + b]);
            const float ff = sigf(Gs[(16 + jl) * 66 + b]);
            const float gv = tanhfast(Gs[(32 + jl) * 66 + b]);
            const float oo = sigf(Gs[(48 + jl) * 66 + b]);
            float ccv = ff * cs[jl * 64 + b] + ii * gv;
            float hh = oo * tanhfast(ccv);
            hh *= m; ccv *= m;
            cs[jl * 64 + b] = ccv;
            hv[e] = hh;
        }
        const int pg = c * 8 + jp;
        uint32_t phh = packbf(hv[0], hv[1]);
        uint32_t pll = packbf(hv[0] - bfr(hv[0]), hv[1] - bfr(hv[1]));
        g_hhi[rb ^ 1][dir][pg][b] = phh;
        g_hlo[rb ^ 1][dir][pg][b] = pll;
        __syncthreads();

        // ---- arrive ---------------------------------------------------------
        unsigned long long tgt;
        if (tid == 0) {
            __threadfence();
            tgt = s_tgt;
            red64(&g_cnt[dir]);
        }

        // ---- gap work -------------------------------------------------------
        if (final_layer) {
            *(float2*)(outext + ((size_t)t * Bn + b) * (2 * Hn)
                       + (size_t)dir * Hn + j0 + 2 * jp) = make_float2(hv[0], hv[1]);
        } else {
            size_t o = ((size_t)t * 512 + (size_t)dir * 256 + pg) * 64 + b;
            g_xphi[o] = phh;
            g_xplo[o] = pll;
        }
        if (s + 1 < Tn) ldxg(dir ? (Tn - 2 - s) : (s + 1), nxt);
        __syncthreads();

        // ---- wait for release ----------------------------------------------
        if (tid == 0) {
            unsigned long long need = tgt << 5;
            unsigned long long v = ld64acq(&g_cnt[dir]);
            while (v < need) { __nanosleep(32); v = ld64acq(&g_cnt[dir]); }
            st64rel(&g_rel[dir], tgt);
            __threadfence();
            s_tgt = tgt + 1ULL;
        }
        __syncthreads();
    }
}

extern "C" void kernel_launch(void* const* d_in, const int* in_sizes, int n_in,
                              void* d_out, int out_size)
{
    const float* x      = (const float*)d_in[0];
    const float* mask   = (const float*)d_in[1];
    const float* f_wih0 = (const float*)d_in[2];
    const float* f_whh0 = (const float*)d_in[3];
    const float* f_bih0 = (const float*)d_in[4];
    const float* f_bhh0 = (const float*)d_in[5];
    const float* b_wih0 = (const float*)d_in[6];
    const float* b_whh0 = (const float*)d_in[7];
    const float* b_bih0 = (const float*)d_in[8];
    const float* b_bhh0 = (const float*)d_in[9];
    const float* f_wih1 = (const float*)d_in[10];
    const float* f_whh1 = (const float*)d_in[11];
    const float* f_bih1 = (const float*)d_in[12];
    const float* f_bhh1 = (const float*)d_in[13];
    const float* b_wih1 = (const float*)d_in[14];
    const float* b_whh1 = (const float*)d_in[15];
    const float* b_bih1 = (const float*)d_in[16];
    const float* b_bhh1 = (const float*)d_in[17];
    float* out = (float*)d_out;

    cudaFuncSetAttribute(input_gemm_mma,
                         cudaFuncAttributeMaxDynamicSharedMemorySize, IN_SMEM);
    cudaFuncSetAttribute(lstm_rec_mma,
                         cudaFuncAttributeMaxDynamicSharedMemorySize, REC_SMEM);

    uint32_t* whi = nullptr; uint32_t* wlo = nullptr;
    cudaGetSymbolAddress((void**)&whi, g_wphi);
    cudaGetSymbolAddress((void**)&wlo, g_wplo);

    pack_w<<<2048, 256>>>(f_wih0, whi, wlo);
    pack_w<<<2048, 256>>>(b_wih0, whi + 524288, wlo + 524288);
    pack_w<<<4096, 256>>>(f_wih1, whi + 1048576, wlo + 1048576);
    pack_w<<<4096, 256>>>(b_wih1, whi + 2097152, wlo + 2097152);
    pack_x<<<512, 256>>>(x);

    dim3 g(G4 / 128, Tn);
    input_gemm_mma<<<g, 256, IN_SMEM>>>(whi, wlo, f_bih0, f_bhh0, 256, 0);
    input_gemm_mma<<<g, 256, IN_SMEM>>>(whi + 524288, wlo + 524288, b_bih0, b_bhh0, 256, 1);
    lstm_rec_mma<<<64, 512, REC_SMEM>>>(f_whh0, b_whh0, mask, out, 0);

    input_gemm_mma<<<g, 256, IN_SMEM>>>(whi + 1048576, wlo + 1048576, f_bih1, f_bhh1, 512, 0);
    input_gemm_mma<<<g, 256, IN_SMEM>>>(whi + 2097152, wlo + 2097152, b_bih1, b_bhh1, 512, 1);
    lstm_rec_mma<<<64, 512, REC_SMEM>>>(f_whh1, b_whh1, mask, out, 1);
}

// round 15
// speedup vs baseline: 1.2270x; 1.2270x over previous
#include <cuda_runtime.h>
#include <cuda_bf16.h>
#include <math.h>
#include <stdint.h>

#define Tn 512
#define Bn 64
#define Hn 512
#define G4 2048
#define REC_CTAS 128

__device__ float    g_xg[2ULL * Tn * G4 * Bn];       // [dir][t][gate_row][b]
__device__ uint32_t g_xphi[(size_t)Tn * 512 * 64];   // [t][kpair][b]
__device__ uint32_t g_xplo[(size_t)Tn * 512 * 64];
__device__ uint32_t g_wphi[3145728];
__device__ uint32_t g_wplo[3145728];
__device__ uint32_t g_hhi[2][2][256][64];            // [buf][dir][jpair][b]
__device__ uint32_t g_hlo[2][2][256][64];
__device__ unsigned long long g_cnt[2] = {0ULL, 0ULL};
__device__ unsigned long long g_rel[2] = {0ULL, 0ULL};

__device__ __forceinline__ void mma16(float* c, const uint32_t* a, uint32_t b0, uint32_t b1) {
    asm volatile("mma.sync.aligned.m16n8k16.row.col.f32.bf16.bf16.f32 "
        "{%0,%1,%2,%3}, {%4,%5,%6,%7}, {%8,%9}, {%0,%1,%2,%3};\n"
        : "+f"(c[0]), "+f"(c[1]), "+f"(c[2]), "+f"(c[3])
        : "r"(a[0]), "r"(a[1]), "r"(a[2]), "r"(a[3]), "r"(b0), "r"(b1));
}
__device__ __forceinline__ uint32_t packbf(float a, float b) {
    __nv_bfloat16 x = __float2bfloat16_rn(a), y = __float2bfloat16_rn(b);
    return ((uint32_t)__bfloat16_as_ushort(y) << 16) | __bfloat16_as_ushort(x);
}
__device__ __forceinline__ float bfr(float v) {
    return __bfloat162float(__float2bfloat16_rn(v));
}
__device__ __forceinline__ float sigf(float x) {
    return __fdividef(1.0f, 1.0f + __expf(-x));
}
__device__ __forceinline__ float tanhfast(float x) {
    x = fminf(fmaxf(x, -15.0f), 15.0f);
    float t = __expf(-2.0f * x);
    return __fdividef(1.0f - t, 1.0f + t);
}
__device__ __forceinline__ unsigned long long ld64acq(const unsigned long long* p) {
    unsigned long long v;
    asm volatile("ld.acquire.gpu.global.u64 %0, [%1];" : "=l"(v) : "l"(p));
    return v;
}
__device__ __forceinline__ void red64(unsigned long long* p) {
    asm volatile("red.relaxed.gpu.global.add.u64 [%0], 1;" :: "l"(p) : "memory");
}
__device__ __forceinline__ void st64rel(unsigned long long* p, unsigned long long v) {
    asm volatile("st.relaxed.gpu.global.u64 [%0], %1;" :: "l"(p), "l"(v));
}

// ---- pack W_ih ---------------------------------------------------------------
__global__ void pack_w(const float* __restrict__ W, uint32_t* __restrict__ hi,
                       uint32_t* __restrict__ lo)
{
    size_t idx = (size_t)blockIdx.x * 256 + threadIdx.x;
    float2 w = *(const float2*)(W + 2 * idx);
    hi[idx] = packbf(w.x, w.y);
    lo[idx] = packbf(w.x - bfr(w.x), w.y - bfr(w.y));
}

// ---- pack x ------------------------------------------------------------------
__global__ __launch_bounds__(256, 4) void pack_x(const float* __restrict__ x)
{
    __shared__ float smx[64 * 68];
    const int t = blockIdx.x, tid = threadIdx.x;
    for (int kb = 0; kb < 512; kb += 64) {
        __syncthreads();
#pragma unroll
        for (int i = 0; i < 4; ++i) {
            int idx = tid + i * 256, b = idx >> 4, f = idx & 15;
            float4 v = *(const float4*)(x + ((size_t)t * 64 + b) * 512 + kb + 4 * f);
            *(float4*)(smx + b * 68 + 4 * f) = v;
        }
        __syncthreads();
#pragma unroll
        for (int i = 0; i < 8; ++i) {
            int idx = tid + i * 256, kp = idx >> 6, b = idx & 63;
            float v0 = smx[b * 68 + 2 * kp], v1 = smx[b * 68 + 2 * kp + 1];
            size_t o = ((size_t)t * 512 + (kb >> 1) + kp) * 64 + b;
            g_xphi[o] = packbf(v0, v1);
            g_xplo[o] = packbf(v0 - bfr(v0), v1 - bfr(v1));
        }
    }
}

// ---- input GEMM: bf16x3, prepacked (unchanged) -------------------------------
#define AST 20
#define IN_SMEM (14848 * 4)

__global__ __launch_bounds__(256, 2)
void input_gemm_mma(const uint32_t* __restrict__ Whi, const uint32_t* __restrict__ Wlo,
                    const float* __restrict__ bih, const float* __restrict__ bhh,
                    int KP, int dir)
{
    extern __shared__ uint32_t sm[];
    uint32_t *AH = sm, *AL = sm + 5120, *BH = sm + 10240, *BL = sm + 12544;
    __shared__ float sbias[128];

    const int t = blockIdx.y, n0 = blockIdx.x * 128;
    const int tid = threadIdx.x, wid = tid >> 5, lane = tid & 31;
    const int gid = lane >> 2, tg = lane & 3;
    const int wm = wid >> 1, wn = wid & 1;
    const int NC = KP >> 4;

    if (tid < 128) sbias[tid] = bih[n0 + tid] + bhh[n0 + tid];
    const uint32_t* XH = g_xphi + (size_t)t * 512 * 64;
    const uint32_t* XL = g_xplo + (size_t)t * 512 * 64;

    uint4 ar[4], br[2];
    float acc[2][4][4];
#pragma unroll
    for (int a = 0; a < 2; ++a)
#pragma unroll
        for (int b = 0; b < 4; ++b)
#pragma unroll
            for (int c = 0; c < 4; ++c) acc[a][b][c] = 0.f;

    auto ldc = [&](int s) {
        const int k0 = s * 16;
#pragma unroll
        for (int i = 0; i < 4; ++i) {
            int j = tid + (i & 1) * 256, r = j >> 2, c = j & 3;
            const uint32_t* src = (i >> 1) ? Wlo : Whi;
            ar[i] = *(const uint4*)(src + (size_t)(n0 + r) * KP + k0 + 4 * c);
        }
#pragma unroll
        for (int i = 0; i < 2; ++i) {
            int r = tid >> 4, c = tid & 15;
            const uint32_t* src = i ? XL : XH;
            br[i] = *(const uint4*)(src + (size_t)(k0 + r) * 64 + 4 * c);
        }
    };
    auto stc = [&](int p) {
#pragma unroll
        for (int i = 0; i < 4; ++i) {
            int j = tid + (i & 1) * 256, r = j >> 2, c = j & 3;
            uint32_t* dst = (i >> 1) ? AL : AH;
            *(uint4*)(dst + p * 2560 + r * AST + 4 * c) = ar[i];
        }
#pragma unroll
        for (int i = 0; i < 2; ++i) {
            int r = tid >> 4, c = tid & 15;
            uint32_t* dst = i ? BL : BH;
            *(uint4*)(dst + p * 1152 + r * 72 + 4 * c) = br[i];
        }
    };

    ldc(0); stc(0); __syncthreads();

    for (int s = 0; s < NC; ++s) {
        const int p = s & 1;
        if (s + 1 < NC) ldc(s + 1);
        const uint32_t* Ah = AH + p * 2560;
        const uint32_t* Al = AL + p * 2560;
        const uint32_t* Bh = BH + p * 1152;
        const uint32_t* Bl = BL + p * 1152;
#pragma unroll
        for (int ks = 0; ks < 2; ++ks) {
            const int kb = ks * 8;
            uint32_t ahi[2][4], alo[2][4];
#pragma unroll
            for (int mt = 0; mt < 2; ++mt) {
                int r = wm * 32 + mt * 16 + gid;
                ahi[mt][0] = Ah[r * AST + kb + tg];
                ahi[mt][1] = Ah[(r + 8) * AST + kb + tg];
                ahi[mt][2] = Ah[r * AST + kb + tg + 4];
                ahi[mt][3] = Ah[(r + 8) * AST + kb + tg + 4];
                alo[mt][0] = Al[r * AST + kb + tg];
                alo[mt][1] = Al[(r + 8) * AST + kb + tg];
                alo[mt][2] = Al[r * AST + kb + tg + 4];
                alo[mt][3] = Al[(r + 8) * AST + kb + tg + 4];
            }
#pragma unroll
            for (int nt = 0; nt < 4; ++nt) {
                int col = wn * 32 + nt * 8 + gid;
                uint32_t bh0 = Bh[(kb + tg) * 72 + col];
                uint32_t bh1 = Bh[(kb + tg + 4) * 72 + col];
                uint32_t bl0 = Bl[(kb + tg) * 72 + col];
                uint32_t bl1 = Bl[(kb + tg + 4) * 72 + col];
#pragma unroll
                for (int mt = 0; mt < 2; ++mt) {
                    mma16(acc[mt][nt], ahi[mt], bh0, bh1);
                    mma16(acc[mt][nt], ahi[mt], bl0, bl1);
                    mma16(acc[mt][nt], alo[mt], bh0, bh1);
                }
            }
        }
        __syncthreads();
        if (s + 1 < NC) { stc(1 - p); __syncthreads(); }
    }

    float* xgd = g_xg + (size_t)dir * Tn * G4 * Bn + (size_t)t * G4 * Bn;
#pragma unroll
    for (int mt = 0; mt < 2; ++mt) {
#pragma unroll
        for (int half = 0; half < 2; ++half) {
            int m = wm * 32 + mt * 16 + gid + half * 8;
            float bias = sbias[m];
            float* row = xgd + (size_t)(n0 + m) * Bn;
#pragma unroll
            for (int nt = 0; nt < 4; ++nt) {
                int b = wn * 32 + nt * 8 + 2 * tg;
                *(float2*)(row + b) = make_float2(acc[mt][nt][2 * half] + bias,
                                                  acc[mt][nt][2 * half + 1] + bias);
            }
        }
    }
}

// ---- recurrent kernel: R13 + 2-phase chunk pipeline (2 syncs in mainloop) ----
#define W2HI_OFF 0
#define W2LO_OFF 8448
#define B_HI_OFF 16896
#define B_LO_OFF 35328
#define GS_OFF   53760
#define CS_OFF   55872
#define MSK_OFF  56384
#define REC_SMEM (56448 * 4)

__global__ __launch_bounds__(256, 1)
void lstm_rec_mma(const float* __restrict__ whh_f, const float* __restrict__ whh_b,
                  const float* __restrict__ mask, float* __restrict__ outext,
                  int final_layer)
{
    extern __shared__ uint32_t smw[];
    uint32_t* W2hi = smw + W2HI_OFF;
    uint32_t* W2lo = smw + W2LO_OFF;
    uint32_t* Bhi  = smw + B_HI_OFF;
    uint32_t* Blo  = smw + B_LO_OFF;
    float*    Gs   = (float*)(smw + GS_OFF);
    float*    cs   = (float*)(smw + CS_OFF);
    float*    msk  = (float*)(smw + MSK_OFF);
    __shared__ unsigned long long s_tgt;

    const int cta = blockIdx.x, tid = threadIdx.x;
    const int dir = cta >> 6;
    const int c   = cta & 63;
    const int j0  = c * 8;
    const int lane = tid & 31, wid = tid >> 5;
    const int gid = lane >> 2, tg = lane & 3;
    const int wm = wid >> 2, wn = wid & 3;
    const int colb = wn * 16;

    const float* __restrict__ Whh = dir ? whh_b : whh_f;
    const float* __restrict__ xgd = g_xg + (size_t)dir * Tn * G4 * Bn;

    if (tid == 0) s_tgt = ld64acq(&g_rel[dir]) + 1ULL;

    for (int i = tid; i < 8192; i += 256) {
        int r = i >> 8, p = i & 255;
        int grow = (r >> 3) * Hn + j0 + (r & 7);
        float2 w = *(const float2*)(Whh + (size_t)grow * Hn + 2 * p);
        int a = r * 264 + (p >> 3) * 8 + 2 * (p & 3) + ((p >> 2) & 1);
        W2hi[a] = packbf(w.x, w.y);
        W2lo[a] = packbf(w.x - bfr(w.x), w.y - bfr(w.y));
    }
    {
        int p = tid >> 6, b = tid & 63;
        g_hhi[0][dir][(j0 >> 1) + p][b] = 0u;
        g_hlo[0][dir][(j0 >> 1) + p][b] = 0u;
    }
    for (int i = tid; i < 512; i += 256) cs[i] = 0.0f;
    __syncthreads();
    if (tid == 0) {
        __threadfence();
        unsigned long long tgt = s_tgt;
        red64(&g_cnt[dir]);
        unsigned long long need = tgt << 6;
        unsigned long long v = ld64acq(&g_cnt[dir]);
        while (v < need) { __nanosleep(32); v = ld64acq(&g_cnt[dir]); }
        st64rel(&g_rel[dir], tgt);
        __threadfence();
        s_tgt = tgt + 1ULL;
    }
    __syncthreads();

    float nxt[2][4];
    auto ldxg = [&](int t, float v[2][4]) {
        const size_t xb = (size_t)t * G4 * Bn;
        const int jlo = j0 + gid;
        const float* p0 = xgd + xb + ((size_t)(2 * wm) * Hn + jlo) * Bn;
        const float* p1 = xgd + xb + ((size_t)(2 * wm + 1) * Hn + jlo) * Bn;
#pragma unroll
        for (int nt = 0; nt < 2; ++nt) {
            int col = colb + nt * 8 + 2 * tg;
            float2 u = *(const float2*)(p0 + col);
            float2 w = *(const float2*)(p1 + col);
            v[nt][0] = u.x; v[nt][1] = u.y; v[nt][2] = w.x; v[nt][3] = w.y;
        }
    };
    ldxg(dir ? (Tn - 1) : 0, nxt);

    for (int s = 0; s < Tn; ++s) {
        const int t  = dir ? (Tn - 1 - s) : s;
        const int rb = s & 1;
        if (tid < 16)
            ((float4*)msk)[tid] = ((const float4*)(mask + (size_t)t * Bn))[tid];

        float c0[2][4];
#pragma unroll
        for (int nt = 0; nt < 2; ++nt)
#pragma unroll
            for (int e = 0; e < 4; ++e) c0[nt][e] = nxt[nt][e];

        const uint32_t* srcHi = &g_hhi[rb][dir][0][0];
        const uint32_t* srcLo = &g_hlo[rb][dir][0][0];

        uint4 ph[4], pl[4];
        auto pollload = [&](int ch) {
#pragma unroll
            for (int i = 0; i < 4; ++i) {
                int idx = tid + i * 256, q = idx >> 4, c4 = (idx & 15) * 4;
                int ap = ch * 64 + q;
                ph[i] = *(const uint4*)(srcHi + (size_t)ap * 64 + c4);
                pl[i] = *(const uint4*)(srcLo + (size_t)ap * 64 + c4);
            }
        };
        auto store = [&](int ch) {
#pragma unroll
            for (int i = 0; i < 4; ++i) {
                int idx = tid + i * 256, q = idx >> 4, c4 = (idx & 15) * 4;
                int ap = ch * 64 + q;
                *(uint4*)(Bhi + (size_t)ap * 72 + c4) = ph[i];
                *(uint4*)(Blo + (size_t)ap * 72 + c4) = pl[i];
            }
        };

        const uint2* A2h = (const uint2*)W2hi;
        const uint2* A2l = (const uint2*)W2lo;

        auto mmach = [&](int ch) {
#pragma unroll
            for (int kt = 0; kt < 8; ++kt) {
                const int g  = ch * 8 + kt;
                const int ra = wm * 16 + gid;
                const int i0 = ra * 132 + g * 4 + tg;
                uint2 h0 = A2h[i0];
                uint2 h1 = A2h[i0 + 8 * 132];
                uint2 l0 = A2l[i0];
                uint2 l1 = A2l[i0 + 8 * 132];
                uint32_t ahi[4] = { h0.x, h1.x, h0.y, h1.y };
                uint32_t alo[4] = { l0.x, l1.x, l0.y, l1.y };
                const int qb = ch * 64 + kt * 8;
#pragma unroll
                for (int nt = 0; nt < 2; ++nt) {
                    const int col = colb + nt * 8 + gid;
                    uint32_t bh0 = Bhi[(qb + tg) * 72 + col];
                    uint32_t bh1 = Bhi[(qb + tg + 4) * 72 + col];
                    uint32_t bl0 = Blo[(qb + tg) * 72 + col];
                    uint32_t bl1 = Blo[(qb + tg + 4) * 72 + col];
                    mma16(c0[nt], ahi, bh0, bh1);
                    mma16(c0[nt], ahi, bl0, bl1);
                    mma16(c0[nt], alo, bh0, bh1);
                }
            }
        };

        // 2-phase schedule: stage 0,1 -> sync -> [stage 2,3 under mma 0,1] -> sync -> mma 2,3
        pollload(0); store(0);
        pollload(1); store(1);
        __syncthreads();
        pollload(2);
        mmach(0);
        store(2);
        pollload(3);
        mmach(1);
        store(3);
        __syncthreads();
        mmach(2);
        mmach(3);

#pragma unroll
        for (int nt = 0; nt < 2; ++nt) {
            int col = colb + nt * 8 + 2 * tg;
            int r = wm * 16 + gid;
            *(float2*)&Gs[r * 66 + col]       = make_float2(c0[nt][0], c0[nt][1]);
            *(float2*)&Gs[(r + 8) * 66 + col] = make_float2(c0[nt][2], c0[nt][3]);
        }
        __syncthreads();

        // ---- epilogue part 1: compute h, store ONLY g_h ----------------------
        const int jp = tid >> 6, b = tid & 63;
        const float m = msk[b];
        float hv[2];
#pragma unroll
        for (int e = 0; e < 2; ++e) {
            const int jl = 2 * jp + e;
            const float ii = sigf(Gs[jl * 66 + b]);
            const float ff = sigf(Gs[(8 + jl) * 66 + b]);
            const float gv = tanhfast(Gs[(16 + jl) * 66 + b]);
            const float oo = sigf(Gs[(24 + jl) * 66 + b]);
            float ccv = ff * cs[jl * 64 + b] + ii * gv;
            float hh = oo * tanhfast(ccv);
            hh *= m; ccv *= m;
            cs[jl * 64 + b] = ccv;
            hv[e] = hh;
        }
        const int pg = (j0 >> 1) + jp;
        uint32_t phh = packbf(hv[0], hv[1]);
        uint32_t pll = packbf(hv[0] - bfr(hv[0]), hv[1] - bfr(hv[1]));
        g_hhi[rb ^ 1][dir][pg][b] = phh;
        g_hlo[rb ^ 1][dir][pg][b] = pll;
        __syncthreads();

        // ---- arrive ----------------------------------------------------------
        unsigned long long tgt;
        if (tid == 0) {
            __threadfence();
            tgt = s_tgt;
            red64(&g_cnt[dir]);
        }

        // ---- gap work --------------------------------------------------------
        if (final_layer) {
            *(float2*)(outext + ((size_t)t * Bn + b) * (2 * Hn)
                       + (size_t)dir * Hn + j0 + 2 * jp) = make_float2(hv[0], hv[1]);
        } else {
            size_t o = ((size_t)t * 512 + (size_t)dir * 256 + pg) * 64 + b;
            g_xphi[o] = phh;
            g_xplo[o] = pll;
        }
        if (s + 1 < Tn) ldxg(dir ? (Tn - 2 - s) : (s + 1), nxt);
        __syncthreads();

        // ---- wait for release ------------------------------------------------
        if (tid == 0) {
            unsigned long long need = tgt << 6;
            unsigned long long v = ld64acq(&g_cnt[dir]);
            while (v < need) { __nanosleep(32); v = ld64acq(&g_cnt[dir]); }
            st64rel(&g_rel[dir], tgt);
            __threadfence();
            s_tgt = tgt + 1ULL;
        }
        __syncthreads();
    }
}

extern "C" void kernel_launch(void* const* d_in, const int* in_sizes, int n_in,
                              void* d_out, int out_size)
{
    const float* x      = (const float*)d_in[0];
    const float* mask   = (const float*)d_in[1];
    const float* f_wih0 = (const float*)d_in[2];
    const float* f_whh0 = (const float*)d_in[3];
    const float* f_bih0 = (const float*)d_in[4];
    const float* f_bhh0 = (const float*)d_in[5];
    const float* b_wih0 = (const float*)d_in[6];
    const float* b_whh0 = (const float*)d_in[7];
    const float* b_bih0 = (const float*)d_in[8];
    const float* b_bhh0 = (const float*)d_in[9];
    const float* f_wih1 = (const float*)d_in[10];
    const float* f_whh1 = (const float*)d_in[11];
    const float* f_bih1 = (const float*)d_in[12];
    const float* f_bhh1 = (const float*)d_in[13];
    const float* b_wih1 = (const float*)d_in[14];
    const float* b_whh1 = (const float*)d_in[15];
    const float* b_bih1 = (const float*)d_in[16];
    const float* b_bhh1 = (const float*)d_in[17];
    float* out = (float*)d_out;

    cudaFuncSetAttribute(input_gemm_mma,
                         cudaFuncAttributeMaxDynamicSharedMemorySize, IN_SMEM);
    cudaFuncSetAttribute(lstm_rec_mma,
                         cudaFuncAttributeMaxDynamicSharedMemorySize, REC_SMEM);

    uint32_t* whi = nullptr; uint32_t* wlo = nullptr;
    cudaGetSymbolAddress((void**)&whi, g_wphi);
    cudaGetSymbolAddress((void**)&wlo, g_wplo);

    pack_w<<<2048, 256>>>(f_wih0, whi, wlo);
    pack_w<<<2048, 256>>>(b_wih0, whi + 524288, wlo + 524288);
    pack_w<<<4096, 256>>>(f_wih1, whi + 1048576, wlo + 1048576);
    pack_w<<<4096, 256>>>(b_wih1, whi + 2097152, wlo + 2097152);
    pack_x<<<512, 256>>>(x);

    dim3 g(G4 / 128, Tn);
    input_gemm_mma<<<g, 256, IN_SMEM>>>(whi, wlo, f_bih0, f_bhh0, 256, 0);
    input_gemm_mma<<<g, 256, IN_SMEM>>>(whi + 524288, wlo + 524288, b_bih0, b_bhh0, 256, 1);
    lstm_rec_mma<<<REC_CTAS, 256, REC_SMEM>>>(f_whh0, b_whh0, mask, out, 0);

    input_gemm_mma<<<g, 256, IN_SMEM>>>(whi + 1048576, wlo + 1048576, f_bih1, f_bhh1, 512, 0);
    input_gemm_mma<<<g, 256, IN_SMEM>>>(whi + 2097152, wlo + 2097152, b_bih1, b_bhh1, 512, 1);
    lstm_rec_mma<<<REC_CTAS, 256, REC_SMEM>>>(f_whh1, b_whh1, mask, out, 1);
}

// round 16
// speedup vs baseline: 1.2424x; 1.0126x over previous
#include <cuda_runtime.h>
#include <cuda_bf16.h>
#include <math.h>
#include <stdint.h>

#define Tn 512
#define Bn 64
#define Hn 512
#define G4 2048
#define REC_CTAS 128

__device__ float    g_xg[2ULL * Tn * G4 * Bn];       // [dir][t][gate_row][b]
__device__ uint32_t g_xphi[(size_t)Tn * 512 * 64];   // [t][kpair][b]
__device__ uint32_t g_xplo[(size_t)Tn * 512 * 64];
__device__ uint32_t g_wphi[3145728];
__device__ uint32_t g_wplo[3145728];
__device__ uint32_t g_hhi[2][2][256][64];            // [buf][dir][jpair][b]
__device__ uint32_t g_hlo[2][2][256][64];
__device__ unsigned long long g_cnt[2] = {0ULL, 0ULL};
__device__ unsigned long long g_rel[2] = {0ULL, 0ULL};

__device__ __forceinline__ void mma16(float* c, const uint32_t* a, uint32_t b0, uint32_t b1) {
    asm volatile("mma.sync.aligned.m16n8k16.row.col.f32.bf16.bf16.f32 "
        "{%0,%1,%2,%3}, {%4,%5,%6,%7}, {%8,%9}, {%0,%1,%2,%3};\n"
        : "+f"(c[0]), "+f"(c[1]), "+f"(c[2]), "+f"(c[3])
        : "r"(a[0]), "r"(a[1]), "r"(a[2]), "r"(a[3]), "r"(b0), "r"(b1));
}
__device__ __forceinline__ uint32_t packbf(float a, float b) {
    __nv_bfloat16 x = __float2bfloat16_rn(a), y = __float2bfloat16_rn(b);
    return ((uint32_t)__bfloat16_as_ushort(y) << 16) | __bfloat16_as_ushort(x);
}
__device__ __forceinline__ float bfr(float v) {
    return __bfloat162float(__float2bfloat16_rn(v));
}
__device__ __forceinline__ float sigf(float x) {
    return __fdividef(1.0f, 1.0f + __expf(-x));
}
__device__ __forceinline__ float tanhfast(float x) {
    x = fminf(fmaxf(x, -15.0f), 15.0f);
    float t = __expf(-2.0f * x);
    return __fdividef(1.0f - t, 1.0f + t);
}
__device__ __forceinline__ unsigned long long ld64acq(const unsigned long long* p) {
    unsigned long long v;
    asm volatile("ld.acquire.gpu.global.u64 %0, [%1];" : "=l"(v) : "l"(p));
    return v;
}
__device__ __forceinline__ void red64(unsigned long long* p) {
    asm volatile("red.relaxed.gpu.global.add.u64 [%0], 1;" :: "l"(p) : "memory");
}
__device__ __forceinline__ void st64rel(unsigned long long* p, unsigned long long v) {
    asm volatile("st.relaxed.gpu.global.u64 [%0], %1;" :: "l"(p), "l"(v));
}

// ---- pack W_ih ---------------------------------------------------------------
__global__ void pack_w(const float* __restrict__ W, uint32_t* __restrict__ hi,
                       uint32_t* __restrict__ lo)
{
    size_t idx = (size_t)blockIdx.x * 256 + threadIdx.x;
    float2 w = *(const float2*)(W + 2 * idx);
    hi[idx] = packbf(w.x, w.y);
    lo[idx] = packbf(w.x - bfr(w.x), w.y - bfr(w.y));
}

// ---- pack x ------------------------------------------------------------------
__global__ __launch_bounds__(256, 4) void pack_x(const float* __restrict__ x)
{
    __shared__ float smx[64 * 68];
    const int t = blockIdx.x, tid = threadIdx.x;
    for (int kb = 0; kb < 512; kb += 64) {
        __syncthreads();
#pragma unroll
        for (int i = 0; i < 4; ++i) {
            int idx = tid + i * 256, b = idx >> 4, f = idx & 15;
            float4 v = *(const float4*)(x + ((size_t)t * 64 + b) * 512 + kb + 4 * f);
            *(float4*)(smx + b * 68 + 4 * f) = v;
        }
        __syncthreads();
#pragma unroll
        for (int i = 0; i < 8; ++i) {
            int idx = tid + i * 256, kp = idx >> 6, b = idx & 63;
            float v0 = smx[b * 68 + 2 * kp], v1 = smx[b * 68 + 2 * kp + 1];
            size_t o = ((size_t)t * 512 + (kb >> 1) + kp) * 64 + b;
            g_xphi[o] = packbf(v0, v1);
            g_xplo[o] = packbf(v0 - bfr(v0), v1 - bfr(v1));
        }
    }
}

// ---- input GEMM: bf16x3, prepacked (unchanged) -------------------------------
#define AST 20
#define IN_SMEM (14848 * 4)

__global__ __launch_bounds__(256, 2)
void input_gemm_mma(const uint32_t* __restrict__ Whi, const uint32_t* __restrict__ Wlo,
                    const float* __restrict__ bih, const float* __restrict__ bhh,
                    int KP, int dir)
{
    extern __shared__ uint32_t sm[];
    uint32_t *AH = sm, *AL = sm + 5120, *BH = sm + 10240, *BL = sm + 12544;
    __shared__ float sbias[128];

    const int t = blockIdx.y, n0 = blockIdx.x * 128;
    const int tid = threadIdx.x, wid = tid >> 5, lane = tid & 31;
    const int gid = lane >> 2, tg = lane & 3;
    const int wm = wid >> 1, wn = wid & 1;
    const int NC = KP >> 4;

    if (tid < 128) sbias[tid] = bih[n0 + tid] + bhh[n0 + tid];
    const uint32_t* XH = g_xphi + (size_t)t * 512 * 64;
    const uint32_t* XL = g_xplo + (size_t)t * 512 * 64;

    uint4 ar[4], br[2];
    float acc[2][4][4];
#pragma unroll
    for (int a = 0; a < 2; ++a)
#pragma unroll
        for (int b = 0; b < 4; ++b)
#pragma unroll
            for (int c = 0; c < 4; ++c) acc[a][b][c] = 0.f;

    auto ldc = [&](int s) {
        const int k0 = s * 16;
#pragma unroll
        for (int i = 0; i < 4; ++i) {
            int j = tid + (i & 1) * 256, r = j >> 2, c = j & 3;
            const uint32_t* src = (i >> 1) ? Wlo : Whi;
            ar[i] = *(const uint4*)(src + (size_t)(n0 + r) * KP + k0 + 4 * c);
        }
#pragma unroll
        for (int i = 0; i < 2; ++i) {
            int r = tid >> 4, c = tid & 15;
            const uint32_t* src = i ? XL : XH;
            br[i] = *(const uint4*)(src + (size_t)(k0 + r) * 64 + 4 * c);
        }
    };
    auto stc = [&](int p) {
#pragma unroll
        for (int i = 0; i < 4; ++i) {
            int j = tid + (i & 1) * 256, r = j >> 2, c = j & 3;
            uint32_t* dst = (i >> 1) ? AL : AH;
            *(uint4*)(dst + p * 2560 + r * AST + 4 * c) = ar[i];
        }
#pragma unroll
        for (int i = 0; i < 2; ++i) {
            int r = tid >> 4, c = tid & 15;
            uint32_t* dst = i ? BL : BH;
            *(uint4*)(dst + p * 1152 + r * 72 + 4 * c) = br[i];
        }
    };

    ldc(0); stc(0); __syncthreads();

    for (int s = 0; s < NC; ++s) {
        const int p = s & 1;
        if (s + 1 < NC) ldc(s + 1);
        const uint32_t* Ah = AH + p * 2560;
        const uint32_t* Al = AL + p * 2560;
        const uint32_t* Bh = BH + p * 1152;
        const uint32_t* Bl = BL + p * 1152;
#pragma unroll
        for (int ks = 0; ks < 2; ++ks) {
            const int kb = ks * 8;
            uint32_t ahi[2][4], alo[2][4];
#pragma unroll
            for (int mt = 0; mt < 2; ++mt) {
                int r = wm * 32 + mt * 16 + gid;
                ahi[mt][0] = Ah[r * AST + kb + tg];
                ahi[mt][1] = Ah[(r + 8) * AST + kb + tg];
                ahi[mt][2] = Ah[r * AST + kb + tg + 4];
                ahi[mt][3] = Ah[(r + 8) * AST + kb + tg + 4];
                alo[mt][0] = Al[r * AST + kb + tg];
                alo[mt][1] = Al[(r + 8) * AST + kb + tg];
                alo[mt][2] = Al[r * AST + kb + tg + 4];
                alo[mt][3] = Al[(r + 8) * AST + kb + tg + 4];
            }
#pragma unroll
            for (int nt = 0; nt < 4; ++nt) {
                int col = wn * 32 + nt * 8 + gid;
                uint32_t bh0 = Bh[(kb + tg) * 72 + col];
                uint32_t bh1 = Bh[(kb + tg + 4) * 72 + col];
                uint32_t bl0 = Bl[(kb + tg) * 72 + col];
                uint32_t bl1 = Bl[(kb + tg + 4) * 72 + col];
#pragma unroll
                for (int mt = 0; mt < 2; ++mt) {
                    mma16(acc[mt][nt], ahi[mt], bh0, bh1);
                    mma16(acc[mt][nt], ahi[mt], bl0, bl1);
                    mma16(acc[mt][nt], alo[mt], bh0, bh1);
                }
            }
        }
        __syncthreads();
        if (s + 1 < NC) { stc(1 - p); __syncthreads(); }
    }

    float* xgd = g_xg + (size_t)dir * Tn * G4 * Bn + (size_t)t * G4 * Bn;
#pragma unroll
    for (int mt = 0; mt < 2; ++mt) {
#pragma unroll
        for (int half = 0; half < 2; ++half) {
            int m = wm * 32 + mt * 16 + gid + half * 8;
            float bias = sbias[m];
            float* row = xgd + (size_t)(n0 + m) * Bn;
#pragma unroll
            for (int nt = 0; nt < 4; ++nt) {
                int b = wn * 32 + nt * 8 + 2 * tg;
                *(float2*)(row + b) = make_float2(acc[mt][nt][2 * half] + bias,
                                                  acc[mt][nt][2 * half + 1] + bias);
            }
        }
    }
}

// ---- recurrent kernel: R15 + 3-way accumulator split, one fewer sync ---------
#define W2HI_OFF 0
#define W2LO_OFF 8448
#define B_HI_OFF 16896
#define B_LO_OFF 35328
#define GS_OFF   53760
#define CS_OFF   55872
#define MSK_OFF  56384
#define REC_SMEM (56448 * 4)

__global__ __launch_bounds__(256, 1)
void lstm_rec_mma(const float* __restrict__ whh_f, const float* __restrict__ whh_b,
                  const float* __restrict__ mask, float* __restrict__ outext,
                  int final_layer)
{
    extern __shared__ uint32_t smw[];
    uint32_t* W2hi = smw + W2HI_OFF;
    uint32_t* W2lo = smw + W2LO_OFF;
    uint32_t* Bhi  = smw + B_HI_OFF;
    uint32_t* Blo  = smw + B_LO_OFF;
    float*    Gs   = (float*)(smw + GS_OFF);
    float*    cs   = (float*)(smw + CS_OFF);
    float*    msk  = (float*)(smw + MSK_OFF);
    __shared__ unsigned long long s_tgt;

    const int cta = blockIdx.x, tid = threadIdx.x;
    const int dir = cta >> 6;
    const int c   = cta & 63;
    const int j0  = c * 8;
    const int lane = tid & 31, wid = tid >> 5;
    const int gid = lane >> 2, tg = lane & 3;
    const int wm = wid >> 2, wn = wid & 3;
    const int colb = wn * 16;

    const float* __restrict__ Whh = dir ? whh_b : whh_f;
    const float* __restrict__ xgd = g_xg + (size_t)dir * Tn * G4 * Bn;

    if (tid == 0) s_tgt = ld64acq(&g_rel[dir]) + 1ULL;

    for (int i = tid; i < 8192; i += 256) {
        int r = i >> 8, p = i & 255;
        int grow = (r >> 3) * Hn + j0 + (r & 7);
        float2 w = *(const float2*)(Whh + (size_t)grow * Hn + 2 * p);
        int a = r * 264 + (p >> 3) * 8 + 2 * (p & 3) + ((p >> 2) & 1);
        W2hi[a] = packbf(w.x, w.y);
        W2lo[a] = packbf(w.x - bfr(w.x), w.y - bfr(w.y));
    }
    {
        int p = tid >> 6, b = tid & 63;
        g_hhi[0][dir][(j0 >> 1) + p][b] = 0u;
        g_hlo[0][dir][(j0 >> 1) + p][b] = 0u;
    }
    for (int i = tid; i < 512; i += 256) cs[i] = 0.0f;
    __syncthreads();
    if (tid == 0) {
        __threadfence();
        unsigned long long tgt = s_tgt;
        red64(&g_cnt[dir]);
        unsigned long long need = tgt << 6;
        unsigned long long v = ld64acq(&g_cnt[dir]);
        while (v < need) { __nanosleep(32); v = ld64acq(&g_cnt[dir]); }
        st64rel(&g_rel[dir], tgt);
        __threadfence();
        s_tgt = tgt + 1ULL;
    }
    __syncthreads();

    float nxt[2][4];
    auto ldxg = [&](int t, float v[2][4]) {
        const size_t xb = (size_t)t * G4 * Bn;
        const int jlo = j0 + gid;
        const float* p0 = xgd + xb + ((size_t)(2 * wm) * Hn + jlo) * Bn;
        const float* p1 = xgd + xb + ((size_t)(2 * wm + 1) * Hn + jlo) * Bn;
#pragma unroll
        for (int nt = 0; nt < 2; ++nt) {
            int col = colb + nt * 8 + 2 * tg;
            float2 u = *(const float2*)(p0 + col);
            float2 w = *(const float2*)(p1 + col);
            v[nt][0] = u.x; v[nt][1] = u.y; v[nt][2] = w.x; v[nt][3] = w.y;
        }
    };
    ldxg(dir ? (Tn - 1) : 0, nxt);

    for (int s = 0; s < Tn; ++s) {
        const int t  = dir ? (Tn - 1 - s) : s;
        const int rb = s & 1;
        if (tid < 16)
            ((float4*)msk)[tid] = ((const float4*)(mask + (size_t)t * Bn))[tid];

        // 3 independent accumulator sets: cA = xg + hi*hi, cB = hi*lo, cC = lo*hi
        float cA[2][4], cB[2][4], cC[2][4];
#pragma unroll
        for (int nt = 0; nt < 2; ++nt)
#pragma unroll
            for (int e = 0; e < 4; ++e) {
                cA[nt][e] = nxt[nt][e];
                cB[nt][e] = 0.0f;
                cC[nt][e] = 0.0f;
            }

        const uint32_t* srcHi = &g_hhi[rb][dir][0][0];
        const uint32_t* srcLo = &g_hlo[rb][dir][0][0];

        uint4 ph[4], pl[4];
        auto pollload = [&](int ch) {
#pragma unroll
            for (int i = 0; i < 4; ++i) {
                int idx = tid + i * 256, q = idx >> 4, c4 = (idx & 15) * 4;
                int ap = ch * 64 + q;
                ph[i] = *(const uint4*)(srcHi + (size_t)ap * 64 + c4);
                pl[i] = *(const uint4*)(srcLo + (size_t)ap * 64 + c4);
            }
        };
        auto store = [&](int ch) {
#pragma unroll
            for (int i = 0; i < 4; ++i) {
                int idx = tid + i * 256, q = idx >> 4, c4 = (idx & 15) * 4;
                int ap = ch * 64 + q;
                *(uint4*)(Bhi + (size_t)ap * 72 + c4) = ph[i];
                *(uint4*)(Blo + (size_t)ap * 72 + c4) = pl[i];
            }
        };

        const uint2* A2h = (const uint2*)W2hi;
        const uint2* A2l = (const uint2*)W2lo;

        auto mmach = [&](int ch) {
#pragma unroll
            for (int kt = 0; kt < 8; ++kt) {
                const int g  = ch * 8 + kt;
                const int ra = wm * 16 + gid;
                const int i0 = ra * 132 + g * 4 + tg;
                uint2 h0 = A2h[i0];
                uint2 h1 = A2h[i0 + 8 * 132];
                uint2 l0 = A2l[i0];
                uint2 l1 = A2l[i0 + 8 * 132];
                uint32_t ahi[4] = { h0.x, h1.x, h0.y, h1.y };
                uint32_t alo[4] = { l0.x, l1.x, l0.y, l1.y };
                const int qb = ch * 64 + kt * 8;
#pragma unroll
                for (int nt = 0; nt < 2; ++nt) {
                    const int col = colb + nt * 8 + gid;
                    uint32_t bh0 = Bhi[(qb + tg) * 72 + col];
                    uint32_t bh1 = Bhi[(qb + tg + 4) * 72 + col];
                    uint32_t bl0 = Blo[(qb + tg) * 72 + col];
                    uint32_t bl1 = Blo[(qb + tg + 4) * 72 + col];
                    mma16(cA[nt], ahi, bh0, bh1);
                    mma16(cB[nt], ahi, bl0, bl1);
                    mma16(cC[nt], alo, bh0, bh1);
                }
            }
        };

        // 2-phase schedule (proven in R15)
        pollload(0); store(0);
        pollload(1); store(1);
        __syncthreads();
        pollload(2);
        mmach(0);
        store(2);
        pollload(3);
        mmach(1);
        store(3);
        __syncthreads();
        mmach(2);
        mmach(3);

#pragma unroll
        for (int nt = 0; nt < 2; ++nt) {
            int col = colb + nt * 8 + 2 * tg;
            int r = wm * 16 + gid;
            float s0 = cA[nt][0] + cB[nt][0] + cC[nt][0];
            float s1 = cA[nt][1] + cB[nt][1] + cC[nt][1];
            float s2 = cA[nt][2] + cB[nt][2] + cC[nt][2];
            float s3 = cA[nt][3] + cB[nt][3] + cC[nt][3];
            *(float2*)&Gs[r * 66 + col]       = make_float2(s0, s1);
            *(float2*)&Gs[(r + 8) * 66 + col] = make_float2(s2, s3);
        }
        __syncthreads();

        // ---- epilogue part 1: compute h, store ONLY g_h ----------------------
        const int jp = tid >> 6, b = tid & 63;
        const float m = msk[b];
        float hv[2];
#pragma unroll
        for (int e = 0; e < 2; ++e) {
            const int jl = 2 * jp + e;
            const float ii = sigf(Gs[jl * 66 + b]);
            const float ff = sigf(Gs[(8 + jl) * 66 + b]);
            const float gv = tanhfast(Gs[(16 + jl) * 66 + b]);
            const float oo = sigf(Gs[(24 + jl) * 66 + b]);
            float ccv = ff * cs[jl * 64 + b] + ii * gv;
            float hh = oo * tanhfast(ccv);
            hh *= m; ccv *= m;
            cs[jl * 64 + b] = ccv;
            hv[e] = hh;
        }
        const int pg = (j0 >> 1) + jp;
        uint32_t phh = packbf(hv[0], hv[1]);
        uint32_t pll = packbf(hv[0] - bfr(hv[0]), hv[1] - bfr(hv[1]));
        g_hhi[rb ^ 1][dir][pg][b] = phh;
        g_hlo[rb ^ 1][dir][pg][b] = pll;
        __syncthreads();

        // ---- arrive ----------------------------------------------------------
        unsigned long long tgt;
        if (tid == 0) {
            __threadfence();
            tgt = s_tgt;
            red64(&g_cnt[dir]);
        }

        // ---- gap work (overlaps tid0's wait; no sync before the wait) --------
        if (final_layer) {
            *(float2*)(outext + ((size_t)t * Bn + b) * (2 * Hn)
                       + (size_t)dir * Hn + j0 + 2 * jp) = make_float2(hv[0], hv[1]);
        } else {
            size_t o = ((size_t)t * 512 + (size_t)dir * 256 + pg) * 64 + b;
            g_xphi[o] = phh;
            g_xplo[o] = pll;
        }
        if (s + 1 < Tn) ldxg(dir ? (Tn - 2 - s) : (s + 1), nxt);

        // ---- wait for release ------------------------------------------------
        if (tid == 0) {
            unsigned long long need = tgt << 6;
            unsigned long long v = ld64acq(&g_cnt[dir]);
            while (v < need) { __nanosleep(32); v = ld64acq(&g_cnt[dir]); }
            st64rel(&g_rel[dir], tgt);
            __threadfence();
            s_tgt = tgt + 1ULL;
        }
        __syncthreads();
    }
}

extern "C" void kernel_launch(void* const* d_in, const int* in_sizes, int n_in,
                              void* d_out, int out_size)
{
    const float* x      = (const float*)d_in[0];
    const float* mask   = (const float*)d_in[1];
    const float* f_wih0 = (const float*)d_in[2];
    const float* f_whh0 = (const float*)d_in[3];
    const float* f_bih0 = (const float*)d_in[4];
    const float* f_bhh0 = (const float*)d_in[5];
    const float* b_wih0 = (const float*)d_in[6];
    const float* b_whh0 = (const float*)d_in[7];
    const float* b_bih0 = (const float*)d_in[8];
    const float* b_bhh0 = (const float*)d_in[9];
    const float* f_wih1 = (const float*)d_in[10];
    const float* f_whh1 = (const float*)d_in[11];
    const float* f_bih1 = (const float*)d_in[12];
    const float* f_bhh1 = (const float*)d_in[13];
    const float* b_wih1 = (const float*)d_in[14];
    const float* b_whh1 = (const float*)d_in[15];
    const float* b_bih1 = (const float*)d_in[16];
    const float* b_bhh1 = (const float*)d_in[17];
    float* out = (float*)d_out;

    cudaFuncSetAttribute(input_gemm_mma,
                         cudaFuncAttributeMaxDynamicSharedMemorySize, IN_SMEM);
    cudaFuncSetAttribute(lstm_rec_mma,
                         cudaFuncAttributeMaxDynamicSharedMemorySize, REC_SMEM);

    uint32_t* whi = nullptr; uint32_t* wlo = nullptr;
    cudaGetSymbolAddress((void**)&whi, g_wphi);
    cudaGetSymbolAddress((void**)&wlo, g_wplo);

    pack_w<<<2048, 256>>>(f_wih0, whi, wlo);
    pack_w<<<2048, 256>>>(b_wih0, whi + 524288, wlo + 524288);
    pack_w<<<4096, 256>>>(f_wih1, whi + 1048576, wlo + 1048576);
    pack_w<<<4096, 256>>>(b_wih1, whi + 2097152, wlo + 2097152);
    pack_x<<<512, 256>>>(x);

    dim3 g(G4 / 128, Tn);
    input_gemm_mma<<<g, 256, IN_SMEM>>>(whi, wlo, f_bih0, f_bhh0, 256, 0);
    input_gemm_mma<<<g, 256, IN_SMEM>>>(whi + 524288, wlo + 524288, b_bih0, b_bhh0, 256, 1);
    lstm_rec_mma<<<REC_CTAS, 256, REC_SMEM>>>(f_whh0, b_whh0, mask, out, 0);

    input_gemm_mma<<<g, 256, IN_SMEM>>>(whi + 1048576, wlo + 1048576, f_bih1, f_bhh1, 512, 0);
    input_gemm_mma<<<g, 256, IN_SMEM>>>(whi + 2097152, wlo + 2097152, b_bih1, b_bhh1, 512, 1);
    lstm_rec_mma<<<REC_CTAS, 256, REC_SMEM>>>(f_whh1, b_whh1, mask, out, 1);
}

// round 17
// speedup vs baseline: 1.3217x; 1.0638x over previous
#include <cuda_runtime.h>
#include <cuda_bf16.h>
#include <cuda_fp16.h>
#include <math.h>
#include <stdint.h>

#define Tn 512
#define Bn 64
#define Hn 512
#define G4 2048
#define REC_CTAS 128

__device__ float    g_xg[2ULL * Tn * G4 * Bn];       // [dir][t][gate_row][b]
__device__ uint32_t g_xphi[(size_t)Tn * 512 * 64];   // [t][kpair][b]  (bf16 pairs)
__device__ uint32_t g_xplo[(size_t)Tn * 512 * 64];
__device__ uint32_t g_wphi[3145728];
__device__ uint32_t g_wplo[3145728];
__device__ uint32_t g_hhi[2][2][256][64];            // [buf][dir][jpair][b] (fp16 pairs)
__device__ uint32_t g_hlo[2][2][256][64];
__device__ unsigned long long g_cnt[2] = {0ULL, 0ULL};
__device__ unsigned long long g_rel[2] = {0ULL, 0ULL};

__device__ __forceinline__ void mma16(float* c, const uint32_t* a, uint32_t b0, uint32_t b1) {
    asm volatile("mma.sync.aligned.m16n8k16.row.col.f32.bf16.bf16.f32 "
        "{%0,%1,%2,%3}, {%4,%5,%6,%7}, {%8,%9}, {%0,%1,%2,%3};\n"
        : "+f"(c[0]), "+f"(c[1]), "+f"(c[2]), "+f"(c[3])
        : "r"(a[0]), "r"(a[1]), "r"(a[2]), "r"(a[3]), "r"(b0), "r"(b1));
}
__device__ __forceinline__ void mma16h(float* c, const uint32_t* a, uint32_t b0, uint32_t b1) {
    asm volatile("mma.sync.aligned.m16n8k16.row.col.f32.f16.f16.f32 "
        "{%0,%1,%2,%3}, {%4,%5,%6,%7}, {%8,%9}, {%0,%1,%2,%3};\n"
        : "+f"(c[0]), "+f"(c[1]), "+f"(c[2]), "+f"(c[3])
        : "r"(a[0]), "r"(a[1]), "r"(a[2]), "r"(a[3]), "r"(b0), "r"(b1));
}
__device__ __forceinline__ uint32_t packbf(float a, float b) {
    __nv_bfloat16 x = __float2bfloat16_rn(a), y = __float2bfloat16_rn(b);
    return ((uint32_t)__bfloat16_as_ushort(y) << 16) | __bfloat16_as_ushort(x);
}
__device__ __forceinline__ float bfr(float v) {
    return __bfloat162float(__float2bfloat16_rn(v));
}
__device__ __forceinline__ uint32_t packh(float a, float b) {
    return ((uint32_t)__half_as_ushort(__float2half_rn(b)) << 16)
         | __half_as_ushort(__float2half_rn(a));
}
__device__ __forceinline__ float hfr(float v) {
    return __half2float(__float2half_rn(v));
}
__device__ __forceinline__ float sigf(float x) {
    return __fdividef(1.0f, 1.0f + __expf(-x));
}
__device__ __forceinline__ float tanhfast(float x) {
    x = fminf(fmaxf(x, -15.0f), 15.0f);
    float t = __expf(-2.0f * x);
    return __fdividef(1.0f - t, 1.0f + t);
}
__device__ __forceinline__ unsigned long long ld64acq(const unsigned long long* p) {
    unsigned long long v;
    asm volatile("ld.acquire.gpu.global.u64 %0, [%1];" : "=l"(v) : "l"(p));
    return v;
}
__device__ __forceinline__ void red64(unsigned long long* p) {
    asm volatile("red.relaxed.gpu.global.add.u64 [%0], 1;" :: "l"(p) : "memory");
}
__device__ __forceinline__ void st64rel(unsigned long long* p, unsigned long long v) {
    asm volatile("st.relaxed.gpu.global.u64 [%0], %1;" :: "l"(p), "l"(v));
}

// ---- pack W_ih (bf16 pairs, for input GEMM) ----------------------------------
__global__ void pack_w(const float* __restrict__ W, uint32_t* __restrict__ hi,
                       uint32_t* __restrict__ lo)
{
    size_t idx = (size_t)blockIdx.x * 256 + threadIdx.x;
    float2 w = *(const float2*)(W + 2 * idx);
    hi[idx] = packbf(w.x, w.y);
    lo[idx] = packbf(w.x - bfr(w.x), w.y - bfr(w.y));
}

// ---- pack x (bf16 pairs) ------------------------------------------------------
__global__ __launch_bounds__(256, 4) void pack_x(const float* __restrict__ x)
{
    __shared__ float smx[64 * 68];
    const int t = blockIdx.x, tid = threadIdx.x;
    for (int kb = 0; kb < 512; kb += 64) {
        __syncthreads();
#pragma unroll
        for (int i = 0; i < 4; ++i) {
            int idx = tid + i * 256, b = idx >> 4, f = idx & 15;
            float4 v = *(const float4*)(x + ((size_t)t * 64 + b) * 512 + kb + 4 * f);
            *(float4*)(smx + b * 68 + 4 * f) = v;
        }
        __syncthreads();
#pragma unroll
        for (int i = 0; i < 8; ++i) {
            int idx = tid + i * 256, kp = idx >> 6, b = idx & 63;
            float v0 = smx[b * 68 + 2 * kp], v1 = smx[b * 68 + 2 * kp + 1];
            size_t o = ((size_t)t * 512 + (kb >> 1) + kp) * 64 + b;
            g_xphi[o] = packbf(v0, v1);
            g_xplo[o] = packbf(v0 - bfr(v0), v1 - bfr(v1));
        }
    }
}

// ---- input GEMM: bf16x3, prepacked (unchanged) -------------------------------
#define AST 20
#define IN_SMEM (14848 * 4)

__global__ __launch_bounds__(256, 2)
void input_gemm_mma(const uint32_t* __restrict__ Whi, const uint32_t* __restrict__ Wlo,
                    const float* __restrict__ bih, const float* __restrict__ bhh,
                    int KP, int dir)
{
    extern __shared__ uint32_t sm[];
    uint32_t *AH = sm, *AL = sm + 5120, *BH = sm + 10240, *BL = sm + 12544;
    __shared__ float sbias[128];

    const int t = blockIdx.y, n0 = blockIdx.x * 128;
    const int tid = threadIdx.x, wid = tid >> 5, lane = tid & 31;
    const int gid = lane >> 2, tg = lane & 3;
    const int wm = wid >> 1, wn = wid & 1;
    const int NC = KP >> 4;

    if (tid < 128) sbias[tid] = bih[n0 + tid] + bhh[n0 + tid];
    const uint32_t* XH = g_xphi + (size_t)t * 512 * 64;
    const uint32_t* XL = g_xplo + (size_t)t * 512 * 64;

    uint4 ar[4], br[2];
    float acc[2][4][4];
#pragma unroll
    for (int a = 0; a < 2; ++a)
#pragma unroll
        for (int b = 0; b < 4; ++b)
#pragma unroll
            for (int c = 0; c < 4; ++c) acc[a][b][c] = 0.f;

    auto ldc = [&](int s) {
        const int k0 = s * 16;
#pragma unroll
        for (int i = 0; i < 4; ++i) {
            int j = tid + (i & 1) * 256, r = j >> 2, c = j & 3;
            const uint32_t* src = (i >> 1) ? Wlo : Whi;
            ar[i] = *(const uint4*)(src + (size_t)(n0 + r) * KP + k0 + 4 * c);
        }
#pragma unroll
        for (int i = 0; i < 2; ++i) {
            int r = tid >> 4, c = tid & 15;
            const uint32_t* src = i ? XL : XH;
            br[i] = *(const uint4*)(src + (size_t)(k0 + r) * 64 + 4 * c);
        }
    };
    auto stc = [&](int p) {
#pragma unroll
        for (int i = 0; i < 4; ++i) {
            int j = tid + (i & 1) * 256, r = j >> 2, c = j & 3;
            uint32_t* dst = (i >> 1) ? AL : AH;
            *(uint4*)(dst + p * 2560 + r * AST + 4 * c) = ar[i];
        }
#pragma unroll
        for (int i = 0; i < 2; ++i) {
            int r = tid >> 4, c = tid & 15;
            uint32_t* dst = i ? BL : BH;
            *(uint4*)(dst + p * 1152 + r * 72 + 4 * c) = br[i];
        }
    };

    ldc(0); stc(0); __syncthreads();

    for (int s = 0; s < NC; ++s) {
        const int p = s & 1;
        if (s + 1 < NC) ldc(s + 1);
        const uint32_t* Ah = AH + p * 2560;
        const uint32_t* Al = AL + p * 2560;
        const uint32_t* Bh = BH + p * 1152;
        const uint32_t* Bl = BL + p * 1152;
#pragma unroll
        for (int ks = 0; ks < 2; ++ks) {
            const int kb = ks * 8;
            uint32_t ahi[2][4], alo[2][4];
#pragma unroll
            for (int mt = 0; mt < 2; ++mt) {
                int r = wm * 32 + mt * 16 + gid;
                ahi[mt][0] = Ah[r * AST + kb + tg];
                ahi[mt][1] = Ah[(r + 8) * AST + kb + tg];
                ahi[mt][2] = Ah[r * AST + kb + tg + 4];
                ahi[mt][3] = Ah[(r + 8) * AST + kb + tg + 4];
                alo[mt][0] = Al[r * AST + kb + tg];
                alo[mt][1] = Al[(r + 8) * AST + kb + tg];
                alo[mt][2] = Al[r * AST + kb + tg + 4];
                alo[mt][3] = Al[(r + 8) * AST + kb + tg + 4];
            }
#pragma unroll
            for (int nt = 0; nt < 4; ++nt) {
                int col = wn * 32 + nt * 8 + gid;
                uint32_t bh0 = Bh[(kb + tg) * 72 + col];
                uint32_t bh1 = Bh[(kb + tg + 4) * 72 + col];
                uint32_t bl0 = Bl[(kb + tg) * 72 + col];
                uint32_t bl1 = Bl[(kb + tg + 4) * 72 + col];
#pragma unroll
                for (int mt = 0; mt < 2; ++mt) {
                    mma16(acc[mt][nt], ahi[mt], bh0, bh1);
                    mma16(acc[mt][nt], ahi[mt], bl0, bl1);
                    mma16(acc[mt][nt], alo[mt], bh0, bh1);
                }
            }
        }
        __syncthreads();
        if (s + 1 < NC) { stc(1 - p); __syncthreads(); }
    }

    float* xgd = g_xg + (size_t)dir * Tn * G4 * Bn + (size_t)t * G4 * Bn;
#pragma unroll
    for (int mt = 0; mt < 2; ++mt) {
#pragma unroll
        for (int half = 0; half < 2; ++half) {
            int m = wm * 32 + mt * 16 + gid + half * 8;
            float bias = sbias[m];
            float* row = xgd + (size_t)(n0 + m) * Bn;
#pragma unroll
            for (int nt = 0; nt < 4; ++nt) {
                int b = wn * 32 + nt * 8 + 2 * tg;
                *(float2*)(row + b) = make_float2(acc[mt][nt][2 * half] + bias,
                                                  acc[mt][nt][2 * half + 1] + bias);
            }
        }
    }
}

// ---- recurrent kernel: fp16 2-pass (W single plane, h hi/lo pair) ------------
#define W2HI_OFF 0
#define B_HI_OFF 8448
#define B_LO_OFF 26880
#define GS_OFF   45312
#define CS_OFF   47424
#define MSK_OFF  47936
#define REC_SMEM (48000 * 4)

__global__ __launch_bounds__(256, 1)
void lstm_rec_mma(const float* __restrict__ whh_f, const float* __restrict__ whh_b,
                  const float* __restrict__ mask, float* __restrict__ outext,
                  int final_layer)
{
    extern __shared__ uint32_t smw[];
    uint32_t* W2hi = smw + W2HI_OFF;
    uint32_t* Bhi  = smw + B_HI_OFF;
    uint32_t* Blo  = smw + B_LO_OFF;
    float*    Gs   = (float*)(smw + GS_OFF);
    float*    cs   = (float*)(smw + CS_OFF);
    float*    msk  = (float*)(smw + MSK_OFF);
    __shared__ unsigned long long s_tgt;

    const int cta = blockIdx.x, tid = threadIdx.x;
    const int dir = cta >> 6;
    const int c   = cta & 63;
    const int j0  = c * 8;
    const int lane = tid & 31, wid = tid >> 5;
    const int gid = lane >> 2, tg = lane & 3;
    const int wm = wid >> 2, wn = wid & 3;
    const int colb = wn * 16;

    const float* __restrict__ Whh = dir ? whh_b : whh_f;
    const float* __restrict__ xgd = g_xg + (size_t)dir * Tn * G4 * Bn;

    if (tid == 0) s_tgt = ld64acq(&g_rel[dir]) + 1ULL;

    // pack W_hh slice: single fp16 plane, u64-paired layout (same addressing)
    for (int i = tid; i < 8192; i += 256) {
        int r = i >> 8, p = i & 255;
        int grow = (r >> 3) * Hn + j0 + (r & 7);
        float2 w = *(const float2*)(Whh + (size_t)grow * Hn + 2 * p);
        int a = r * 264 + (p >> 3) * 8 + 2 * (p & 3) + ((p >> 2) & 1);
        W2hi[a] = packh(w.x, w.y);
    }
    {
        int p = tid >> 6, b = tid & 63;
        g_hhi[0][dir][(j0 >> 1) + p][b] = 0u;
        g_hlo[0][dir][(j0 >> 1) + p][b] = 0u;
    }
    for (int i = tid; i < 512; i += 256) cs[i] = 0.0f;
    __syncthreads();
    if (tid == 0) {
        __threadfence();
        unsigned long long tgt = s_tgt;
        red64(&g_cnt[dir]);
        unsigned long long need = tgt << 6;
        unsigned long long v = ld64acq(&g_cnt[dir]);
        while (v < need) { __nanosleep(32); v = ld64acq(&g_cnt[dir]); }
        st64rel(&g_rel[dir], tgt);
        __threadfence();
        s_tgt = tgt + 1ULL;
    }
    __syncthreads();

    float nxt[2][4];
    auto ldxg = [&](int t, float v[2][4]) {
        const size_t xb = (size_t)t * G4 * Bn;
        const int jlo = j0 + gid;
        const float* p0 = xgd + xb + ((size_t)(2 * wm) * Hn + jlo) * Bn;
        const float* p1 = xgd + xb + ((size_t)(2 * wm + 1) * Hn + jlo) * Bn;
#pragma unroll
        for (int nt = 0; nt < 2; ++nt) {
            int col = colb + nt * 8 + 2 * tg;
            float2 u = *(const float2*)(p0 + col);
            float2 w = *(const float2*)(p1 + col);
            v[nt][0] = u.x; v[nt][1] = u.y; v[nt][2] = w.x; v[nt][3] = w.y;
        }
    };
    ldxg(dir ? (Tn - 1) : 0, nxt);

    for (int s = 0; s < Tn; ++s) {
        const int t  = dir ? (Tn - 1 - s) : s;
        const int rb = s & 1;
        if (tid < 16)
            ((float4*)msk)[tid] = ((const float4*)(mask + (size_t)t * Bn))[tid];

        // 2 independent accumulator sets: cA = xg + Whi*hhi, cB = Whi*hlo
        float cA[2][4], cB[2][4];
#pragma unroll
        for (int nt = 0; nt < 2; ++nt)
#pragma unroll
            for (int e = 0; e < 4; ++e) {
                cA[nt][e] = nxt[nt][e];
                cB[nt][e] = 0.0f;
            }

        const uint32_t* srcHi = &g_hhi[rb][dir][0][0];
        const uint32_t* srcLo = &g_hlo[rb][dir][0][0];

        uint4 ph[4], pl[4];
        auto pollload = [&](int ch) {
#pragma unroll
            for (int i = 0; i < 4; ++i) {
                int idx = tid + i * 256, q = idx >> 4, c4 = (idx & 15) * 4;
                int ap = ch * 64 + q;
                ph[i] = *(const uint4*)(srcHi + (size_t)ap * 64 + c4);
                pl[i] = *(const uint4*)(srcLo + (size_t)ap * 64 + c4);
            }
        };
        auto store = [&](int ch) {
#pragma unroll
            for (int i = 0; i < 4; ++i) {
                int idx = tid + i * 256, q = idx >> 4, c4 = (idx & 15) * 4;
                int ap = ch * 64 + q;
                *(uint4*)(Bhi + (size_t)ap * 72 + c4) = ph[i];
                *(uint4*)(Blo + (size_t)ap * 72 + c4) = pl[i];
            }
        };

        const uint2* A2h = (const uint2*)W2hi;

        auto mmach = [&](int ch) {
#pragma unroll
            for (int kt = 0; kt < 8; ++kt) {
                const int g  = ch * 8 + kt;
                const int ra = wm * 16 + gid;
                const int i0 = ra * 132 + g * 4 + tg;
                uint2 h0 = A2h[i0];
                uint2 h1 = A2h[i0 + 8 * 132];
                uint32_t ahi[4] = { h0.x, h1.x, h0.y, h1.y };
                const int qb = ch * 64 + kt * 8;
#pragma unroll
                for (int nt = 0; nt < 2; ++nt) {
                    const int col = colb + nt * 8 + gid;
                    uint32_t bh0 = Bhi[(qb + tg) * 72 + col];
                    uint32_t bh1 = Bhi[(qb + tg + 4) * 72 + col];
                    uint32_t bl0 = Blo[(qb + tg) * 72 + col];
                    uint32_t bl1 = Blo[(qb + tg + 4) * 72 + col];
                    mma16h(cA[nt], ahi, bh0, bh1);
                    mma16h(cB[nt], ahi, bl0, bl1);
                }
            }
        };

        // 2-phase schedule (proven in R15)
        pollload(0); store(0);
        pollload(1); store(1);
        __syncthreads();
        pollload(2);
        mmach(0);
        store(2);
        pollload(3);
        mmach(1);
        store(3);
        __syncthreads();
        mmach(2);
        mmach(3);

#pragma unroll
        for (int nt = 0; nt < 2; ++nt) {
            int col = colb + nt * 8 + 2 * tg;
            int r = wm * 16 + gid;
            float s0 = cA[nt][0] + cB[nt][0];
            float s1 = cA[nt][1] + cB[nt][1];
            float s2 = cA[nt][2] + cB[nt][2];
            float s3 = cA[nt][3] + cB[nt][3];
            *(float2*)&Gs[r * 66 + col]       = make_float2(s0, s1);
            *(float2*)&Gs[(r + 8) * 66 + col] = make_float2(s2, s3);
        }
        __syncthreads();

        // ---- epilogue part 1: compute h, store ONLY g_h (fp16 pairs) ---------
        const int jp = tid >> 6, b = tid & 63;
        const float m = msk[b];
        float hv[2];
#pragma unroll
        for (int e = 0; e < 2; ++e) {
            const int jl = 2 * jp + e;
            const float ii = sigf(Gs[jl * 66 + b]);
            const float ff = sigf(Gs[(8 + jl) * 66 + b]);
            const float gv = tanhfast(Gs[(16 + jl) * 66 + b]);
            const float oo = sigf(Gs[(24 + jl) * 66 + b]);
            float ccv = ff * cs[jl * 64 + b] + ii * gv;
            float hh = oo * tanhfast(ccv);
            hh *= m; ccv *= m;
            cs[jl * 64 + b] = ccv;
            hv[e] = hh;
        }
        const int pg = (j0 >> 1) + jp;
        g_hhi[rb ^ 1][dir][pg][b] = packh(hv[0], hv[1]);
        g_hlo[rb ^ 1][dir][pg][b] = packh(hv[0] - hfr(hv[0]), hv[1] - hfr(hv[1]));
        __syncthreads();

        // ---- arrive ----------------------------------------------------------
        unsigned long long tgt;
        if (tid == 0) {
            __threadfence();
            tgt = s_tgt;
            red64(&g_cnt[dir]);
        }

        // ---- gap work (overlaps tid0's wait) ---------------------------------
        if (final_layer) {
            *(float2*)(outext + ((size_t)t * Bn + b) * (2 * Hn)
                       + (size_t)dir * Hn + j0 + 2 * jp) = make_float2(hv[0], hv[1]);
        } else {
            size_t o = ((size_t)t * 512 + (size_t)dir * 256 + pg) * 64 + b;
            g_xphi[o] = packbf(hv[0], hv[1]);
            g_xplo[o] = packbf(hv[0] - bfr(hv[0]), hv[1] - bfr(hv[1]));
        }
        if (s + 1 < Tn) ldxg(dir ? (Tn - 2 - s) : (s + 1), nxt);

        // ---- wait for release ------------------------------------------------
        if (tid == 0) {
            unsigned long long need = tgt << 6;
            unsigned long long v = ld64acq(&g_cnt[dir]);
            while (v < need) { __nanosleep(32); v = ld64acq(&g_cnt[dir]); }
            st64rel(&g_rel[dir], tgt);
            __threadfence();
            s_tgt = tgt + 1ULL;
        }
        __syncthreads();
    }
}

extern "C" void kernel_launch(void* const* d_in, const int* in_sizes, int n_in,
                              void* d_out, int out_size)
{
    const float* x      = (const float*)d_in[0];
    const float* mask   = (const float*)d_in[1];
    const float* f_wih0 = (const float*)d_in[2];
    const float* f_whh0 = (const float*)d_in[3];
    const float* f_bih0 = (const float*)d_in[4];
    const float* f_bhh0 = (const float*)d_in[5];
    const float* b_wih0 = (const float*)d_in[6];
    const float* b_whh0 = (const float*)d_in[7];
    const float* b_bih0 = (const float*)d_in[8];
    const float* b_bhh0 = (const float*)d_in[9];
    const float* f_wih1 = (const float*)d_in[10];
    const float* f_whh1 = (const float*)d_in[11];
    const float* f_bih1 = (const float*)d_in[12];
    const float* f_bhh1 = (const float*)d_in[13];
    const float* b_wih1 = (const float*)d_in[14];
    const float* b_whh1 = (const float*)d_in[15];
    const float* b_bih1 = (const float*)d_in[16];
    const float* b_bhh1 = (const float*)d_in[17];
    float* out = (float*)d_out;

    cudaFuncSetAttribute(input_gemm_mma,
                         cudaFuncAttributeMaxDynamicSharedMemorySize, IN_SMEM);
    cudaFuncSetAttribute(lstm_rec_mma,
                         cudaFuncAttributeMaxDynamicSharedMemorySize, REC_SMEM);

    uint32_t* whi = nullptr; uint32_t* wlo = nullptr;
    cudaGetSymbolAddress((void**)&whi, g_wphi);
    cudaGetSymbolAddress((void**)&wlo, g_wplo);

    pack_w<<<2048, 256>>>(f_wih0, whi, wlo);
    pack_w<<<2048, 256>>>(b_wih0, whi + 524288, wlo + 524288);
    pack_w<<<4096, 256>>>(f_wih1, whi + 1048576, wlo + 1048576);
    pack_w<<<4096, 256>>>(b_wih1, whi + 2097152, wlo + 2097152);
    pack_x<<<512, 256>>>(x);

    dim3 g(G4 / 128, Tn);
    input_gemm_mma<<<g, 256, IN_SMEM>>>(whi, wlo, f_bih0, f_bhh0, 256, 0);
    input_gemm_mma<<<g, 256, IN_SMEM>>>(whi + 524288, wlo + 524288, b_bih0, b_bhh0, 256, 1);
    lstm_rec_mma<<<REC_CTAS, 256, REC_SMEM>>>(f_whh0, b_whh0, mask, out, 0);

    input_gemm_mma<<<g, 256, IN_SMEM>>>(whi + 1048576, wlo + 1048576, f_bih1, f_bhh1, 512, 0);
    input_gemm_mma<<<g, 256, IN_SMEM>>>(whi + 2097152, wlo + 2097152, b_bih1, b_bhh1, 512, 1);
    lstm_rec_mma<<<REC_CTAS, 256, REC_SMEM>>>(f_whh1, b_whh1, mask, out, 1);
}